// round 16
// baseline (speedup 1.0000x reference)
#include <cuda_runtime.h>
#include <cstdint>

// out = X * W[idx][0] + Y * W[idx][1], idx = reward[b,s] in {0,1}
// X,Y: (4,4096,2048) fp32; reward: (4,4096,1) int32; W: (2,2) fp32.
//
// FINAL KERNEL (R6; best of 12 measured variants, reproduced 5x:
// 52.1-54.0us kernel band, 6523-6757 GB/s, bench 61.9-62.5us).
// HBM-bound blend at 96% of the absolute traffic-time floor
// (402.6 MB @ 8 TB/s = 50.3us) for this 2R:1W fp32 stream:
//   - one block = one (b,s) row = 512 contiguous float4
//   - 2 float4/thread at stride 256 -> every LDG/STG is a fully coalesced
//     512B warp wavefront
//   - 4 front-batched loads/thread: peak of the full MLP sweep
//       MLP2 74.7% | MLP4 85% | MLP6 80.5% (64-reg occ cliff)
//       | MLP8 79% (cross-CTA L1tex queue contention)
//   - 32 regs -> ~82% occupancy (the other half of why MLP=4 wins)
//   - single uniform reward load per block; W gather L1-resident
//   - default cache policy (.cs regressed via store-coalescing loss,
//     .lu neutral)
//   - flat 16384-CTA grid (persistent grid regressed via loop
//     serialization; 2-row/3-row/512-thread blocks neutral or worse)

__global__ __launch_bounds__(256)
void blend_kernel_row(const float4* __restrict__ X,
                      const float4* __restrict__ Y,
                      const int* __restrict__ reward,
                      const float* __restrict__ W,
                      float4* __restrict__ out)
{
    int base = blockIdx.x * 512 + threadIdx.x;   // row = blockIdx.x

    int idx = (reward[blockIdx.x] != 0) ? 1 : 0; // uniform across block
    float a = W[2 * idx];
    float b = W[2 * idx + 1];

    // Front-batch 4 global loads (MLP=4).
    float4 x0 = X[base];
    float4 x1 = X[base + 256];
    float4 y0 = Y[base];
    float4 y1 = Y[base + 256];

    float4 o0, o1;
    o0.x = fmaf(x0.x, a, y0.x * b);
    o0.y = fmaf(x0.y, a, y0.y * b);
    o0.z = fmaf(x0.z, a, y0.z * b);
    o0.w = fmaf(x0.w, a, y0.w * b);
    o1.x = fmaf(x1.x, a, y1.x * b);
    o1.y = fmaf(x1.y, a, y1.y * b);
    o1.z = fmaf(x1.z, a, y1.z * b);
    o1.w = fmaf(x1.w, a, y1.w * b);

    out[base]       = o0;
    out[base + 256] = o1;
}

extern "C" void kernel_launch(void* const* d_in, const int* in_sizes, int n_in,
                              void* d_out, int out_size)
{
    const float4* X      = (const float4*)d_in[0];
    const float4* Y      = (const float4*)d_in[1];
    const int*    reward = (const int*)d_in[2];
    const float*  W      = (const float*)d_in[3];
    float4*       out    = (float4*)d_out;

    int n  = out_size;          // 4*4096*2048 = 33554432 fp32
    int n4 = n / 4;             // 8388608 float4
    int blocks = n4 / 512;      // 16384 blocks, one row each (exact)

    blend_kernel_row<<<blocks, 256>>>(X, Y, reward, W, out);
}

// round 17
// speedup vs baseline: 1.0005x; 1.0005x over previous
#include <cuda_runtime.h>
#include <cstdint>

// out = X * W[idx][0] + Y * W[idx][1], idx = reward[b,s] in {0,1}
// X,Y: (4,4096,2048) fp32; reward: (4,4096,1) int32; W: (2,2) fp32.
//
// R6 structure (proven optimal among 128-bit kernels: one block = one row,
// fully coalesced, 64B of loads in flight per thread, default cache policy,
// flat 16384 grid) upgraded to Blackwell 256-bit global accesses
// (ld/st.global.v8.f32, sm_100+): same bytes in flight, HALF the LSU
// dispatches and L1tex wavefront-queue entries per byte — attacks the
// queue-contention term without moving any swept axis.
// Each thread: one v8 X load + one v8 Y load + one v8 store.
// 256 threads x 32B = 8192B = exactly one (b,s) row.

__global__ __launch_bounds__(256)
void blend_kernel_v8(const float* __restrict__ X,
                     const float* __restrict__ Y,
                     const int* __restrict__ reward,
                     const float* __restrict__ W,
                     float* __restrict__ out)
{
    // row = blockIdx.x; thread covers floats [row*2048 + tid*8, +8)
    long long off = (long long)blockIdx.x * 2048 + (long long)threadIdx.x * 8;

    int idx = (reward[blockIdx.x] != 0) ? 1 : 0;   // uniform across block
    float a = W[2 * idx];
    float b = W[2 * idx + 1];

    const float* xp = X + off;
    const float* yp = Y + off;
    float*       op = out + off;

    float x0, x1, x2, x3, x4, x5, x6, x7;
    float y0, y1, y2, y3, y4, y5, y6, y7;

    // Front-batch both 256-bit loads (same 64B in flight as R6's 4x128-bit).
    asm volatile("ld.global.v8.f32 {%0,%1,%2,%3,%4,%5,%6,%7}, [%8];"
                 : "=f"(x0), "=f"(x1), "=f"(x2), "=f"(x3),
                   "=f"(x4), "=f"(x5), "=f"(x6), "=f"(x7)
                 : "l"(xp));
    asm volatile("ld.global.v8.f32 {%0,%1,%2,%3,%4,%5,%6,%7}, [%8];"
                 : "=f"(y0), "=f"(y1), "=f"(y2), "=f"(y3),
                   "=f"(y4), "=f"(y5), "=f"(y6), "=f"(y7)
                 : "l"(yp));

    float o0 = fmaf(x0, a, y0 * b);
    float o1 = fmaf(x1, a, y1 * b);
    float o2 = fmaf(x2, a, y2 * b);
    float o3 = fmaf(x3, a, y3 * b);
    float o4 = fmaf(x4, a, y4 * b);
    float o5 = fmaf(x5, a, y5 * b);
    float o6 = fmaf(x6, a, y6 * b);
    float o7 = fmaf(x7, a, y7 * b);

    asm volatile("st.global.v8.f32 [%0], {%1,%2,%3,%4,%5,%6,%7,%8};"
                 :: "l"(op),
                    "f"(o0), "f"(o1), "f"(o2), "f"(o3),
                    "f"(o4), "f"(o5), "f"(o6), "f"(o7)
                 : "memory");
}

extern "C" void kernel_launch(void* const* d_in, const int* in_sizes, int n_in,
                              void* d_out, int out_size)
{
    const float* X      = (const float*)d_in[0];
    const float* Y      = (const float*)d_in[1];
    const int*   reward = (const int*)d_in[2];
    const float* W      = (const float*)d_in[3];
    float*       out    = (float*)d_out;

    int n      = out_size;      // 4*4096*2048 = 33554432 fp32
    int blocks = n / 2048;      // 16384 blocks, one row each (exact)

    blend_kernel_v8<<<blocks, 256>>>(X, Y, reward, W, out);
}